// round 10
// baseline (speedup 1.0000x reference)
#include <cuda_runtime.h>
#include <math.h>
#include <stdint.h>

#define NN 10000
#define NE 160000
#define ET (NN + NE)

// ---------------- scratch (device globals; referenced by symbol ONLY in device code) ----------------
__device__ float g_feat[NN * 256];     // layer input features (row-major, stride = fin)
__device__ float g_hbuf[NN * 2048];    // h = X @ W   (row-major, stride = H*C)
__device__ float g_fH[NN * 256];       // tf32-hi split of feat (padded stride Kp)
__device__ float g_fL[NN * 256];       // tf32-lo split
__device__ float g_wH[2048 * 256];     // W^T hi split, [HC][Kp] K-major
__device__ float g_wL[2048 * 256];     // W^T lo split
__device__ float g_hs[NN * 16];
__device__ float g_hd[NN * 16];
__device__ int   g_cnt[NN];
__device__ int   g_cur[NN];
__device__ int   g_off[NN + 1];
__device__ int   g_csr[ET];
__device__ float g_cb1[64 * 64 * 64];
__device__ float g_cb2[64 * 64 * 64];
__device__ float g_gf[24];
__device__ unsigned char g_bflags[NN];
__device__ int   g_is64;

__device__ __forceinline__ float selu_f(float v) {
    const float sc = 1.0507009873554805f;
    const float al = 1.6732632423543772f;
    return v > 0.f ? sc * v : sc * al * (expf(v) - 1.f);
}

__device__ __forceinline__ float tf32_hi(float f) {
    return __uint_as_float(__float_as_uint(f) & 0xFFFFE000u);
}

__device__ __forceinline__ int edge_at(const void* ei, int idx) {
    if (g_is64) return (int)((const long long*)ei)[idx];
    return ((const int*)ei)[idx];
}

// ---------------- CSR init + dtype detection ----------------
__global__ void init_detect_k(const void* __restrict__ ei) {
    int i = blockIdx.x * 256 + threadIdx.x;
    if (i < NN) { g_cnt[i] = 1; g_cur[i] = 0; }
    if (blockIdx.x == 0) {
        __shared__ int nz;
        if (threadIdx.x == 0) nz = 0;
        __syncthreads();
        const int* p = (const int*)ei;
        int found = 0;
        for (int j = threadIdx.x; j < 4096; j += 256)
            if (p[2 * j + 1] != 0) found = 1;
        if (found) atomicOr(&nz, 1);
        __syncthreads();
        if (threadIdx.x == 0) g_is64 = nz ? 0 : 1;
    }
}

__global__ void csr_count_k(const void* __restrict__ ei) {
    int e = blockIdx.x * 256 + threadIdx.x;
    if (e < NE) atomicAdd(&g_cnt[edge_at(ei, NE + e)], 1);
}

__global__ void csr_scan_k() {
    __shared__ int wsum[32];
    int tid = threadIdx.x;
    const int per = 10;
    int start = tid * per;
    int s = 0;
#pragma unroll
    for (int j = 0; j < per; j++) { int idx = start + j; if (idx < NN) s += g_cnt[idx]; }
    int lane = tid & 31, warp = tid >> 5;
    int v = s;
#pragma unroll
    for (int o = 1; o < 32; o <<= 1) {
        int t = __shfl_up_sync(0xffffffffu, v, o);
        if (lane >= o) v += t;
    }
    if (lane == 31) wsum[warp] = v;
    __syncthreads();
    if (warp == 0) {
        int w = wsum[lane];
#pragma unroll
        for (int o = 1; o < 32; o <<= 1) {
            int t = __shfl_up_sync(0xffffffffu, w, o);
            if (lane >= o) w += t;
        }
        wsum[lane] = w;
    }
    __syncthreads();
    int base = (warp ? wsum[warp - 1] : 0) + (v - s);
    int run = base;
#pragma unroll
    for (int j = 0; j < per; j++) {
        int idx = start + j;
        if (idx < NN) { g_off[idx] = run; run += g_cnt[idx]; }
    }
    if (tid == 0) g_off[NN] = wsum[31];
}

__global__ void csr_fill_k(const void* __restrict__ ei) {
    int idx = blockIdx.x * 256 + threadIdx.x;
    if (idx >= ET) return;
    int s, d;
    if (idx < NN) { s = idx; d = idx; }
    else {
        int e = idx - NN;
        s = edge_at(ei, e);
        d = edge_at(ei, NE + e);
    }
    int pos = g_off[d] + atomicAdd(&g_cur[d], 1);
    g_csr[pos] = s;
}

// ---------------- CNN ----------------
__global__ void conv3x3_k(const float* __restrict__ ext_in, int in_sel, int out_sel,
                          const float* __restrict__ w, const float* __restrict__ b, int IC) {
    __shared__ float ws[64 * 9];
    const float* in = (in_sel == 0) ? ext_in : (in_sel == 1 ? g_cb1 : g_cb2);
    float* out = (out_sel == 1) ? g_cb1 : g_cb2;
    int oc = blockIdx.y;
    for (int idx = threadIdx.x; idx < IC * 9; idx += 256) ws[idx] = w[oc * IC * 9 + idx];
    __syncthreads();
    int p = blockIdx.x * 256 + threadIdx.x;
    int y = p >> 6, xx = p & 63;
    float acc = b[oc];
    for (int ic = 0; ic < IC; ic++) {
        const float* ip = in + ic * 4096;
        const float* wp = ws + ic * 9;
#pragma unroll
        for (int ky = 0; ky < 3; ky++) {
            int iy = y + ky - 1;
            if ((unsigned)iy >= 64u) continue;
#pragma unroll
            for (int kx = 0; kx < 3; kx++) {
                int ix = xx + kx - 1;
                if ((unsigned)ix >= 64u) continue;
                acc += ip[iy * 64 + ix] * wp[ky * 3 + kx];
            }
        }
    }
    out[oc * 4096 + p] = selu_f(acc);
}

__global__ void avgpool_k() {
    __shared__ float red[256];
    int c = blockIdx.x;
    float s = 0.f;
    for (int p = threadIdx.x; p < 4096; p += 256) s += g_cb2[c * 4096 + p];
    red[threadIdx.x] = s;
    __syncthreads();
    for (int o = 128; o > 0; o >>= 1) {
        if (threadIdx.x < o) red[threadIdx.x] += red[threadIdx.x + o];
        __syncthreads();
    }
    if (threadIdx.x == 0) g_gf[c] = red[0] * (1.f / 4096.f);
}

__global__ void build_in_k(const float* __restrict__ x) {
    int i = blockIdx.x * 256 + threadIdx.x;
    if (i >= NN) return;
    float x0 = x[i * 10], x1 = x[i * 10 + 1];
    unsigned char f = 0;
    if (x0 == 1.f) f |= 1;
    if (x0 == 0.f) f |= 2;
    if (x1 == 0.f) f |= 4;
    if (x1 == 1.f) f |= 8;
    g_bflags[i] = f;
#pragma unroll
    for (int c = 0; c < 24; c++) g_feat[i * 34 + c] = g_gf[c];
#pragma unroll
    for (int c = 0; c < 10; c++) g_feat[i * 34 + 24 + c] = x[i * 10 + c];
}

// ---------------- tf32 split prep ----------------
__global__ void split_feat_k(int fin, int Kp) {
    int idx = blockIdx.x * 256 + threadIdx.x;
    if (idx >= NN * Kp) return;
    int i = idx / Kp, k = idx - i * Kp;
    float f = (k < fin) ? g_feat[i * fin + k] : 0.f;
    float hi = tf32_hi(f);
    g_fH[idx] = hi;
    g_fL[idx] = f - hi;
}

__global__ void split_wt_k(const float* __restrict__ W, int K, int HC, int Kp) {
    int idx = blockIdx.x * 256 + threadIdx.x;
    if (idx >= HC * Kp) return;
    int kp = idx / HC, n = idx - kp * HC;
    float f = (kp < K) ? W[(size_t)kp * HC + n] : 0.f;
    float hi = tf32_hi(f);
    g_wH[(size_t)n * Kp + kp] = hi;
    g_wL[(size_t)n * Kp + kp] = f - hi;
}

// ---------------- mma.sync tf32 GEMM (3xTF32): g_hbuf[N,HC] = feat @ W ----------------
__device__ __forceinline__ void mma_tf32(float& c0, float& c1, float& c2, float& c3,
                                         uint32_t a0, uint32_t a1, uint32_t a2, uint32_t a3,
                                         uint32_t b0, uint32_t b1) {
    asm volatile(
        "mma.sync.aligned.m16n8k8.row.col.f32.tf32.tf32.f32 "
        "{%0,%1,%2,%3}, {%4,%5,%6,%7}, {%8,%9}, {%0,%1,%2,%3};"
        : "+f"(c0), "+f"(c1), "+f"(c2), "+f"(c3)
        : "r"(a0), "r"(a1), "r"(a2), "r"(a3), "r"(b0), "r"(b1));
}

__global__ void __launch_bounds__(256) tc_gemm_k(int Kp, int M) {
    // Block tile: 128(M) x 64(N); 8 warps in 4(M) x 2(N); warp tile 32x32.
    __shared__ float AsH[16][136], AsL[16][136];   // [k][m], pad 8 -> conflict-free frag reads
    __shared__ float BsH[64][20],  BsL[64][20];    // [n][k], pad 4 -> conflict-free frag reads

    const int tid = threadIdx.x;
    const int wid = tid >> 5, lane = tid & 31;
    const int group = lane >> 2, tig = lane & 3;
    const int warpM = wid & 3, warpN = wid >> 2;
    const int row0 = blockIdx.y * 128, col0 = blockIdx.x * 64;

    float acc[2][4][4];
#pragma unroll
    for (int mf = 0; mf < 2; mf++)
#pragma unroll
        for (int nf = 0; nf < 4; nf++)
#pragma unroll
            for (int r = 0; r < 4; r++) acc[mf][nf][r] = 0.f;

    const int nchunks = Kp >> 4;
    for (int ck = 0; ck < nchunks; ck++) {
        int k0 = ck << 4;
        // stage A: 128 rows x 16 k (hi+lo), transposed into [k][m]
        for (int idx = tid; idx < 512; idx += 256) {
            int r = idx >> 2, c = idx & 3;
            int gr = row0 + r;
            float4 vh = make_float4(0.f, 0.f, 0.f, 0.f), vl = vh;
            if (gr < NN) {
                size_t o = (size_t)gr * Kp + k0 + c * 4;
                vh = *(const float4*)&g_fH[o];
                vl = *(const float4*)&g_fL[o];
            }
            int kb = c * 4;
            AsH[kb + 0][r] = vh.x; AsH[kb + 1][r] = vh.y; AsH[kb + 2][r] = vh.z; AsH[kb + 3][r] = vh.w;
            AsL[kb + 0][r] = vl.x; AsL[kb + 1][r] = vl.y; AsL[kb + 2][r] = vl.z; AsL[kb + 3][r] = vl.w;
        }
        // stage B: 64 n x 16 k (hi+lo)
        {
            int n = tid >> 2, c = tid & 3;
            float4 vh = make_float4(0.f, 0.f, 0.f, 0.f), vl = vh;
            if (col0 + n < M) {
                size_t o = (size_t)(col0 + n) * Kp + k0 + c * 4;
                vh = *(const float4*)&g_wH[o];
                vl = *(const float4*)&g_wL[o];
            }
            *(float4*)&BsH[n][c * 4] = vh;
            *(float4*)&BsL[n][c * 4] = vl;
        }
        __syncthreads();

#pragma unroll
        for (int ks = 0; ks < 2; ks++) {
            uint32_t ah[2][4], al[2][4], bh[4][2], bl[4][2];
#pragma unroll
            for (int mf = 0; mf < 2; mf++) {
                int mb = warpM * 32 + mf * 16 + group;
                int kb = ks * 8 + tig;
                ah[mf][0] = __float_as_uint(AsH[kb][mb]);
                ah[mf][1] = __float_as_uint(AsH[kb][mb + 8]);
                ah[mf][2] = __float_as_uint(AsH[kb + 4][mb]);
                ah[mf][3] = __float_as_uint(AsH[kb + 4][mb + 8]);
                al[mf][0] = __float_as_uint(AsL[kb][mb]);
                al[mf][1] = __float_as_uint(AsL[kb][mb + 8]);
                al[mf][2] = __float_as_uint(AsL[kb + 4][mb]);
                al[mf][3] = __float_as_uint(AsL[kb + 4][mb + 8]);
            }
#pragma unroll
            for (int nf = 0; nf < 4; nf++) {
                int nb = warpN * 32 + nf * 8 + group;
                int kb = ks * 8 + tig;
                bh[nf][0] = __float_as_uint(BsH[nb][kb]);
                bh[nf][1] = __float_as_uint(BsH[nb][kb + 4]);
                bl[nf][0] = __float_as_uint(BsL[nb][kb]);
                bl[nf][1] = __float_as_uint(BsL[nb][kb + 4]);
            }
#pragma unroll
            for (int mf = 0; mf < 2; mf++)
#pragma unroll
                for (int nf = 0; nf < 4; nf++) {
                    float* c = acc[mf][nf];
                    mma_tf32(c[0], c[1], c[2], c[3],
                             ah[mf][0], ah[mf][1], ah[mf][2], ah[mf][3], bh[nf][0], bh[nf][1]);
                    mma_tf32(c[0], c[1], c[2], c[3],
                             ah[mf][0], ah[mf][1], ah[mf][2], ah[mf][3], bl[nf][0], bl[nf][1]);
                    mma_tf32(c[0], c[1], c[2], c[3],
                             al[mf][0], al[mf][1], al[mf][2], al[mf][3], bh[nf][0], bh[nf][1]);
                }
        }
        __syncthreads();
    }

    // epilogue: c0/c1 -> (row=group, cols 2tig,2tig+1); c2/c3 -> row=group+8
#pragma unroll
    for (int mf = 0; mf < 2; mf++) {
        int rbase = row0 + warpM * 32 + mf * 16 + group;
#pragma unroll
        for (int nf = 0; nf < 4; nf++) {
            int cbase = col0 + warpN * 32 + nf * 8 + 2 * tig;
            if (cbase < M) {
                if (rbase < NN)
                    *(float2*)&g_hbuf[(size_t)rbase * M + cbase] =
                        make_float2(acc[mf][nf][0], acc[mf][nf][1]);
                if (rbase + 8 < NN)
                    *(float2*)&g_hbuf[(size_t)(rbase + 8) * M + cbase] =
                        make_float2(acc[mf][nf][2], acc[mf][nf][3]);
            }
        }
    }
}

// ---------------- per-node attention dots hs/hd ----------------
__global__ void attn_dots_k(const float* __restrict__ as_, const float* __restrict__ ad_,
                            int H, int C) {
    int i = blockIdx.x;
    int warp = threadIdx.x >> 5, lane = threadIdx.x & 31;
    const float* hrow = g_hbuf + (size_t)i * H * C;
    for (int hh = warp; hh < H; hh += 8) {
        float ps = 0.f, pd = 0.f;
        for (int c = lane; c < C; c += 32) {
            float v = hrow[hh * C + c];
            ps += v * as_[hh * C + c];
            pd += v * ad_[hh * C + c];
        }
#pragma unroll
        for (int o = 16; o; o >>= 1) {
            ps += __shfl_xor_sync(0xffffffffu, ps, o);
            pd += __shfl_xor_sync(0xffffffffu, pd, o);
        }
        if (lane == 0) { g_hs[i * H + hh] = ps; g_hd[i * H + hh] = pd; }
    }
}

// ---------------- GAT aggregation ----------------
template <int H, int C, bool FINAL>
__global__ void gat_agg_k(const float* __restrict__ bias, const float* __restrict__ x,
                          float* __restrict__ outp) {
    constexpr int HC = H * C;
    constexpr int NT = 256;
    constexpr int R = (HC + NT - 1) / NT;
    constexpr int CH = 32;
    __shared__ float s_m[H], s_z[H], s_hdi[H];
    __shared__ int   s_src[CH];
    __shared__ float s_e[CH * H];
    __shared__ float s_agg[HC];

    int i = blockIdx.x;
    int tid = threadIdx.x;
    int e0 = g_off[i];
    int deg = g_off[i + 1] - e0;
    if (tid < H) s_hdi[tid] = g_hd[i * H + tid];
    __syncthreads();

    float m_run = -1e30f, z_run = 0.f;
    for (int c0 = 0; c0 < deg; c0 += CH) {
        int cl = min(CH, deg - c0);
        if (tid < cl) s_src[tid] = g_csr[e0 + c0 + tid];
        __syncthreads();
        for (int idx = tid; idx < cl * H; idx += NT) {
            int ce = idx / H, hh = idx - ce * H;
            float v = g_hs[s_src[ce] * H + hh] + s_hdi[hh];
            s_e[idx] = v > 0.f ? v : 0.2f * v;
        }
        __syncthreads();
        if (tid < H) {
            for (int ce = 0; ce < cl; ce++) {
                float v = s_e[ce * H + tid];
                float mn = fmaxf(m_run, v);
                z_run = z_run * expf(m_run - mn) + expf(v - mn);
                m_run = mn;
            }
        }
        __syncthreads();
    }
    if (tid < H) { s_m[tid] = m_run; s_z[tid] = z_run; }
    __syncthreads();

    float acc[R];
#pragma unroll
    for (int r = 0; r < R; r++) acc[r] = 0.f;

    for (int c0 = 0; c0 < deg; c0 += CH) {
        int cl = min(CH, deg - c0);
        if (tid < cl) s_src[tid] = g_csr[e0 + c0 + tid];
        __syncthreads();
        for (int idx = tid; idx < cl * H; idx += NT) {
            int ce = idx / H, hh = idx - ce * H;
            float v = g_hs[s_src[ce] * H + hh] + s_hdi[hh];
            v = v > 0.f ? v : 0.2f * v;
            s_e[idx] = expf(v - s_m[hh]) / (s_z[hh] + 1e-16f);
        }
        __syncthreads();
        for (int ce = 0; ce < cl; ce++) {
            const float* hrow = g_hbuf + (size_t)s_src[ce] * HC;
#pragma unroll
            for (int r = 0; r < R; r++) {
                int j = tid + r * NT;
                if (HC >= NT * (r + 1) || j < HC)
                    acc[r] += s_e[ce * H + (j / C)] * hrow[j];
            }
        }
        __syncthreads();
    }

#pragma unroll
    for (int r = 0; r < R; r++) {
        int j = tid + r * NT;
        if (HC >= NT * (r + 1) || j < HC) s_agg[j] = acc[r];
    }
    __syncthreads();

    unsigned char f = g_bflags[i];
    for (int c = tid; c < C; c += NT) {
        float v = 0.f;
#pragma unroll
        for (int hh = 0; hh < H; hh++) v += s_agg[hh * C + c];
        v = v * (1.f / H) + bias[c];
        v = selu_f(v);
        if (FINAL) v += x[i * 10 + c];
        if (c == 0)      v = (f & 2) ? 0.f : ((f & 1) ? 1.f : v);
        else if (c == 1) v = (f & 8) ? 1.f : ((f & 4) ? 0.f : v);
        if (FINAL) outp[(size_t)i * C + c] = v;
        else       g_feat[(size_t)i * C + c] = v;
    }
}

// ---------------- host launch ----------------
extern "C" void kernel_launch(void* const* d_in, const int* in_sizes, int n_in,
                              void* d_out, int out_size) {
    const float* x  = (const float*)d_in[0];
    const void*  ei = d_in[1];
    const float* cf = (const float*)d_in[2];
    const float* cw[4]  = {(const float*)d_in[3], (const float*)d_in[5],
                           (const float*)d_in[7], (const float*)d_in[9]};
    const float* cbi[4] = {(const float*)d_in[4], (const float*)d_in[6],
                           (const float*)d_in[8], (const float*)d_in[10]};
    const float *gw[5], *gas[5], *gad[5], *gb[5];
    for (int l = 0; l < 5; l++) {
        gw[l]  = (const float*)d_in[11 + 4 * l];
        gas[l] = (const float*)d_in[12 + 4 * l];
        gad[l] = (const float*)d_in[13 + 4 * l];
        gb[l]  = (const float*)d_in[14 + 4 * l];
    }
    float* out = (float*)d_out;

    init_detect_k<<<(NN + 255) / 256, 256>>>(ei);
    csr_count_k<<<(NE + 255) / 256, 256>>>(ei);
    csr_scan_k<<<1, 1024>>>();
    csr_fill_k<<<(ET + 255) / 256, 256>>>(ei);

    conv3x3_k<<<dim3(16, 16), 256>>>(cf, 0, 1, cw[0], cbi[0], 4);
    conv3x3_k<<<dim3(16, 32), 256>>>(nullptr, 1, 2, cw[1], cbi[1], 16);
    conv3x3_k<<<dim3(16, 64), 256>>>(nullptr, 2, 1, cw[2], cbi[2], 32);
    conv3x3_k<<<dim3(16, 24), 256>>>(nullptr, 1, 2, cw[3], cbi[3], 64);
    avgpool_k<<<24, 256>>>();
    build_in_k<<<(NN + 255) / 256, 256>>>(x);

    const int fins[5] = {34, 64, 128, 256, 128};
    const int Kps[5]  = {64, 64, 128, 256, 128};
    const int Hs[5]   = {8, 16, 8, 8, 16};
    const int Cs[5]   = {64, 128, 256, 128, 2};

    for (int l = 0; l < 5; l++) {
        int HC = Hs[l] * Cs[l];
        int Kp = Kps[l];
        split_feat_k<<<(NN * Kp + 255) / 256, 256>>>(fins[l], Kp);
        split_wt_k<<<(HC * Kp + 255) / 256, 256>>>(gw[l], fins[l], HC, Kp);
        dim3 gg((HC + 63) / 64, (NN + 127) / 128);
        tc_gemm_k<<<gg, 256>>>(Kp, HC);
        attn_dots_k<<<NN, 256>>>(gas[l], gad[l], Hs[l], Cs[l]);
        switch (l) {
            case 0: gat_agg_k<8, 64, false><<<NN, 256>>>(gb[0], x, nullptr); break;
            case 1: gat_agg_k<16, 128, false><<<NN, 256>>>(gb[1], x, nullptr); break;
            case 2: gat_agg_k<8, 256, false><<<NN, 256>>>(gb[2], x, nullptr); break;
            case 3: gat_agg_k<8, 128, false><<<NN, 256>>>(gb[3], x, nullptr); break;
            case 4: gat_agg_k<16, 2, true><<<NN, 256>>>(gb[4], x, out); break;
        }
    }
}

// round 11
// speedup vs baseline: 1.2577x; 1.2577x over previous
#include <cuda_runtime.h>
#include <cuda_fp16.h>
#include <math.h>
#include <stdint.h>

#define NN 10000
#define NE 160000
#define ET (NN + NE)

// ---------------- scratch (device globals; referenced by symbol ONLY in device code) ----------------
__device__ float  g_feat[NN * 256];     // layer input features (row-major, stride = fin)
__device__ __half g_hbufh[NN * 2048];   // h = X @ W  in fp16 (row-major, stride = H*C)
__device__ float  g_hs[NN * 16];
__device__ float  g_hd[NN * 16];
__device__ int    g_cnt[NN];
__device__ int    g_cur[NN];
__device__ int    g_off[NN + 1];
__device__ int    g_csr[ET];
__device__ float  g_cb1[64 * 64 * 64];
__device__ float  g_cb2[64 * 64 * 64];
__device__ float  g_gf[24];
__device__ unsigned char g_bflags[NN];
__device__ int    g_is64;

__device__ __forceinline__ float selu_f(float v) {
    const float sc = 1.0507009873554805f;
    const float al = 1.6732632423543772f;
    return v > 0.f ? sc * v : sc * al * (expf(v) - 1.f);
}

__device__ __forceinline__ int edge_at(const void* ei, int idx) {
    if (g_is64) return (int)((const long long*)ei)[idx];
    return ((const int*)ei)[idx];
}

// ---------------- CSR init + dtype detection ----------------
__global__ void init_detect_k(const void* __restrict__ ei) {
    int i = blockIdx.x * 256 + threadIdx.x;
    if (i < NN) { g_cnt[i] = 1; g_cur[i] = 0; }
    if (blockIdx.x == 0) {
        __shared__ int nz;
        if (threadIdx.x == 0) nz = 0;
        __syncthreads();
        const int* p = (const int*)ei;
        int found = 0;
        for (int j = threadIdx.x; j < 4096; j += 256)
            if (p[2 * j + 1] != 0) found = 1;
        if (found) atomicOr(&nz, 1);
        __syncthreads();
        if (threadIdx.x == 0) g_is64 = nz ? 0 : 1;
    }
}

__global__ void csr_count_k(const void* __restrict__ ei) {
    int e = blockIdx.x * 256 + threadIdx.x;
    if (e < NE) atomicAdd(&g_cnt[edge_at(ei, NE + e)], 1);
}

__global__ void csr_scan_k() {
    __shared__ int wsum[32];
    int tid = threadIdx.x;
    const int per = 10;
    int start = tid * per;
    int s = 0;
#pragma unroll
    for (int j = 0; j < per; j++) { int idx = start + j; if (idx < NN) s += g_cnt[idx]; }
    int lane = tid & 31, warp = tid >> 5;
    int v = s;
#pragma unroll
    for (int o = 1; o < 32; o <<= 1) {
        int t = __shfl_up_sync(0xffffffffu, v, o);
        if (lane >= o) v += t;
    }
    if (lane == 31) wsum[warp] = v;
    __syncthreads();
    if (warp == 0) {
        int w = wsum[lane];
#pragma unroll
        for (int o = 1; o < 32; o <<= 1) {
            int t = __shfl_up_sync(0xffffffffu, w, o);
            if (lane >= o) w += t;
        }
        wsum[lane] = w;
    }
    __syncthreads();
    int base = (warp ? wsum[warp - 1] : 0) + (v - s);
    int run = base;
#pragma unroll
    for (int j = 0; j < per; j++) {
        int idx = start + j;
        if (idx < NN) { g_off[idx] = run; run += g_cnt[idx]; }
    }
    if (tid == 0) g_off[NN] = wsum[31];
}

__global__ void csr_fill_k(const void* __restrict__ ei) {
    int idx = blockIdx.x * 256 + threadIdx.x;
    if (idx >= ET) return;
    int s, d;
    if (idx < NN) { s = idx; d = idx; }
    else {
        int e = idx - NN;
        s = edge_at(ei, e);
        d = edge_at(ei, NE + e);
    }
    int pos = g_off[d] + atomicAdd(&g_cur[d], 1);
    g_csr[pos] = s;
}

// ---------------- CNN ----------------
__global__ void conv3x3_k(const float* __restrict__ ext_in, int in_sel, int out_sel,
                          const float* __restrict__ w, const float* __restrict__ b, int IC) {
    __shared__ float ws[64 * 9];
    const float* in = (in_sel == 0) ? ext_in : (in_sel == 1 ? g_cb1 : g_cb2);
    float* out = (out_sel == 1) ? g_cb1 : g_cb2;
    int oc = blockIdx.y;
    for (int idx = threadIdx.x; idx < IC * 9; idx += 256) ws[idx] = w[oc * IC * 9 + idx];
    __syncthreads();
    int p = blockIdx.x * 256 + threadIdx.x;
    int y = p >> 6, xx = p & 63;
    float acc = b[oc];
    for (int ic = 0; ic < IC; ic++) {
        const float* ip = in + ic * 4096;
        const float* wp = ws + ic * 9;
#pragma unroll
        for (int ky = 0; ky < 3; ky++) {
            int iy = y + ky - 1;
            if ((unsigned)iy >= 64u) continue;
#pragma unroll
            for (int kx = 0; kx < 3; kx++) {
                int ix = xx + kx - 1;
                if ((unsigned)ix >= 64u) continue;
                acc += ip[iy * 64 + ix] * wp[ky * 3 + kx];
            }
        }
    }
    out[oc * 4096 + p] = selu_f(acc);
}

__global__ void avgpool_k() {
    __shared__ float red[256];
    int c = blockIdx.x;
    float s = 0.f;
    for (int p = threadIdx.x; p < 4096; p += 256) s += g_cb2[c * 4096 + p];
    red[threadIdx.x] = s;
    __syncthreads();
    for (int o = 128; o > 0; o >>= 1) {
        if (threadIdx.x < o) red[threadIdx.x] += red[threadIdx.x + o];
        __syncthreads();
    }
    if (threadIdx.x == 0) g_gf[c] = red[0] * (1.f / 4096.f);
}

__global__ void build_in_k(const float* __restrict__ x) {
    int i = blockIdx.x * 256 + threadIdx.x;
    if (i >= NN) return;
    float x0 = x[i * 10], x1 = x[i * 10 + 1];
    unsigned char f = 0;
    if (x0 == 1.f) f |= 1;
    if (x0 == 0.f) f |= 2;
    if (x1 == 0.f) f |= 4;
    if (x1 == 1.f) f |= 8;
    g_bflags[i] = f;
#pragma unroll
    for (int c = 0; c < 24; c++) g_feat[i * 34 + c] = g_gf[c];
#pragma unroll
    for (int c = 0; c < 10; c++) g_feat[i * 34 + 24 + c] = x[i * 10 + c];
}

// ---------------- SGEMM: g_hbufh[N,M] = half( g_feat[N,K] @ B[K,M] ) ----------------
// 128x64 tile, 256 threads, 8x4 accum/thread, double-buffered smem, float4 loads, half stores.
__global__ void __launch_bounds__(256) sgemm_k(const float* __restrict__ B, int N, int K, int M) {
    __shared__ float As[2][16][128];
    __shared__ float Bs[2][16][64];
    int tid = threadIdx.x;
    int tx = tid & 15, ty = tid >> 4;
    int row0 = blockIdx.y * 128, col0 = blockIdx.x * 64;

    int ar = tid & 127;
    int aq = tid >> 7;
    int bk = tid >> 4;
    int bc = (tid & 15) * 4;

    const bool kfull = (K % 16 == 0);
    const int ntiles = (K + 15) / 16;

    float acc[8][4];
#pragma unroll
    for (int i = 0; i < 8; i++)
#pragma unroll
        for (int j = 0; j < 4; j++) acc[i][j] = 0.f;

    float ra[8], rb[4];
    int agr = row0 + ar;
    int bgc = col0 + bc;

    auto load_tile = [&](int kt) {
        int k0 = kt * 16;
        if (kfull) {
            if (agr < N) {
                const float* p = &g_feat[(size_t)agr * K + k0 + aq * 8];
                float4 v0 = *(const float4*)p;
                float4 v1 = *(const float4*)(p + 4);
                ra[0] = v0.x; ra[1] = v0.y; ra[2] = v0.z; ra[3] = v0.w;
                ra[4] = v1.x; ra[5] = v1.y; ra[6] = v1.z; ra[7] = v1.w;
            } else {
#pragma unroll
                for (int j = 0; j < 8; j++) ra[j] = 0.f;
            }
        } else {
#pragma unroll
            for (int j = 0; j < 8; j++) {
                int gk = k0 + aq * 8 + j;
                ra[j] = (agr < N && gk < K) ? g_feat[(size_t)agr * K + gk] : 0.f;
            }
        }
        int gk = k0 + bk;
        if (gk < K && bgc < M) {
            float4 v = *(const float4*)&B[(size_t)gk * M + bgc];
            rb[0] = v.x; rb[1] = v.y; rb[2] = v.z; rb[3] = v.w;
        } else {
#pragma unroll
            for (int j = 0; j < 4; j++) rb[j] = 0.f;
        }
    };
    auto store_tile = [&](int nb) {
#pragma unroll
        for (int j = 0; j < 8; j++) As[nb][aq * 8 + j][ar] = ra[j];
        *(float4*)&Bs[nb][bk][bc] = make_float4(rb[0], rb[1], rb[2], rb[3]);
    };

    load_tile(0);
    store_tile(0);
    __syncthreads();

    for (int kt = 0; kt < ntiles; kt++) {
        int buf = kt & 1;
        bool more = (kt + 1 < ntiles);
        if (more) load_tile(kt + 1);
#pragma unroll
        for (int kk = 0; kk < 16; kk++) {
            float a[8], b[4];
#pragma unroll
            for (int i = 0; i < 8; i++) a[i] = As[buf][kk][ty * 8 + i];
#pragma unroll
            for (int j = 0; j < 4; j++) b[j] = Bs[buf][kk][tx * 4 + j];
#pragma unroll
            for (int i = 0; i < 8; i++)
#pragma unroll
                for (int j = 0; j < 4; j++) acc[i][j] += a[i] * b[j];
        }
        if (more) store_tile(buf ^ 1);
        __syncthreads();
    }

    int gc = col0 + tx * 4;
    if (gc < M) {
#pragma unroll
        for (int i = 0; i < 8; i++) {
            int gr = row0 + ty * 8 + i;
            if (gr < N) {
                __half2 h0 = __floats2half2_rn(acc[i][0], acc[i][1]);
                __half2 h1 = __floats2half2_rn(acc[i][2], acc[i][3]);
                uint2 pk;
                pk.x = *(uint32_t*)&h0;
                pk.y = *(uint32_t*)&h1;
                *(uint2*)&g_hbufh[(size_t)gr * M + gc] = pk;
            }
        }
    }
}

// ---------------- per-node attention dots hs/hd (reads g_hbufh) ----------------
__global__ void attn_dots_k(const float* __restrict__ as_, const float* __restrict__ ad_,
                            int H, int C) {
    int i = blockIdx.x;
    int warp = threadIdx.x >> 5, lane = threadIdx.x & 31;
    const __half2* hrow = (const __half2*)(g_hbufh + (size_t)i * H * C);
    int C2 = C >> 1;
    for (int hh = warp; hh < H; hh += 8) {
        float ps = 0.f, pd = 0.f;
        for (int c2 = lane; c2 < C2; c2 += 32) {
            float2 f = __half22float2(hrow[hh * C2 + c2]);
            int c = 2 * c2;
            ps += f.x * as_[hh * C + c] + f.y * as_[hh * C + c + 1];
            pd += f.x * ad_[hh * C + c] + f.y * ad_[hh * C + c + 1];
        }
#pragma unroll
        for (int o = 16; o; o >>= 1) {
            ps += __shfl_xor_sync(0xffffffffu, ps, o);
            pd += __shfl_xor_sync(0xffffffffu, pd, o);
        }
        if (lane == 0) { g_hs[i * H + hh] = ps; g_hd[i * H + hh] = pd; }
    }
}

// ---------------- GAT aggregation (vectorized fp16 gather) ----------------
// One block per dst. VW halfs per thread per edge row (C % VW == 0, HC <= VW*256).
template <int H, int C, int VW, bool FINAL>
__global__ void gat_agg_k(const float* __restrict__ bias, const float* __restrict__ x,
                          float* __restrict__ outp) {
    constexpr int HC = H * C;
    constexpr int NT = 256;
    constexpr int NV = HC / VW;          // active threads in gather
    constexpr int CH = 32;
    static_assert(NV <= NT, "vector coverage");
    __shared__ float s_m[H], s_z[H], s_hdi[H];
    __shared__ int   s_src[CH];
    __shared__ float s_e[CH * H];
    __shared__ float s_agg[HC];

    int i = blockIdx.x;
    int tid = threadIdx.x;
    int e0 = g_off[i];
    int deg = g_off[i + 1] - e0;
    if (tid < H) s_hdi[tid] = g_hd[i * H + tid];
    __syncthreads();

    // Pass A: online softmax stats per head
    float m_run = -1e30f, z_run = 0.f;
    for (int c0 = 0; c0 < deg; c0 += CH) {
        int cl = min(CH, deg - c0);
        if (tid < cl) s_src[tid] = g_csr[e0 + c0 + tid];
        __syncthreads();
        for (int idx = tid; idx < cl * H; idx += NT) {
            int ce = idx / H, hh = idx - ce * H;
            float v = g_hs[s_src[ce] * H + hh] + s_hdi[hh];
            s_e[idx] = v > 0.f ? v : 0.2f * v;
        }
        __syncthreads();
        if (tid < H) {
            for (int ce = 0; ce < cl; ce++) {
                float v = s_e[ce * H + tid];
                float mn = fmaxf(m_run, v);
                z_run = z_run * expf(m_run - mn) + expf(v - mn);
                m_run = mn;
            }
        }
        __syncthreads();
    }
    if (tid < H) { s_m[tid] = m_run; s_z[tid] = z_run; }
    __syncthreads();

    // Pass B: alpha-weighted vectorized gather of h[src]
    float acc[VW];
#pragma unroll
    for (int v = 0; v < VW; v++) acc[v] = 0.f;
    const int hh_t = (tid * VW) / C;     // head for this thread's channels (valid when tid < NV)

    for (int c0 = 0; c0 < deg; c0 += CH) {
        int cl = min(CH, deg - c0);
        if (tid < cl) s_src[tid] = g_csr[e0 + c0 + tid];
        __syncthreads();
        for (int idx = tid; idx < cl * H; idx += NT) {
            int ce = idx / H, hh = idx - ce * H;
            float v = g_hs[s_src[ce] * H + hh] + s_hdi[hh];
            v = v > 0.f ? v : 0.2f * v;
            s_e[idx] = expf(v - s_m[hh]) / (s_z[hh] + 1e-16f);
        }
        __syncthreads();
        if (tid < NV) {
            for (int ce = 0; ce < cl; ce++) {
                const __half* hrow = g_hbufh + (size_t)s_src[ce] * HC + tid * VW;
                float al = s_e[ce * H + hh_t];
                if (VW == 8) {
                    uint4 pk = *(const uint4*)hrow;
                    float2 f0 = __half22float2(*(__half2*)&pk.x);
                    float2 f1 = __half22float2(*(__half2*)&pk.y);
                    float2 f2 = __half22float2(*(__half2*)&pk.z);
                    float2 f3 = __half22float2(*(__half2*)&pk.w);
                    acc[0] += al * f0.x; acc[1] += al * f0.y;
                    acc[2] += al * f1.x; acc[3] += al * f1.y;
                    acc[4] += al * f2.x; acc[5] += al * f2.y;
                    acc[6] += al * f3.x; acc[7] += al * f3.y;
                } else if (VW == 4) {
                    uint2 pk = *(const uint2*)hrow;
                    float2 f0 = __half22float2(*(__half2*)&pk.x);
                    float2 f1 = __half22float2(*(__half2*)&pk.y);
                    acc[0] += al * f0.x; acc[1] += al * f0.y;
                    acc[2] += al * f1.x; acc[3] += al * f1.y;
                } else {
                    float2 f0 = __half22float2(*(const __half2*)hrow);
                    acc[0] += al * f0.x; acc[1] += al * f0.y;
                }
            }
        }
        __syncthreads();
    }

    if (tid < NV) {
#pragma unroll
        for (int v = 0; v < VW; v++) s_agg[tid * VW + v] = acc[v];
    }
    __syncthreads();

    unsigned char f = g_bflags[i];
    for (int c = tid; c < C; c += NT) {
        float v = 0.f;
#pragma unroll
        for (int hh = 0; hh < H; hh++) v += s_agg[hh * C + c];
        v = v * (1.f / H) + bias[c];
        v = selu_f(v);
        if (FINAL) v += x[i * 10 + c];
        if (c == 0)      v = (f & 2) ? 0.f : ((f & 1) ? 1.f : v);
        else if (c == 1) v = (f & 8) ? 1.f : ((f & 4) ? 0.f : v);
        if (FINAL) outp[(size_t)i * C + c] = v;
        else       g_feat[(size_t)i * C + c] = v;
    }
}

// ---------------- host launch ----------------
extern "C" void kernel_launch(void* const* d_in, const int* in_sizes, int n_in,
                              void* d_out, int out_size) {
    const float* x  = (const float*)d_in[0];
    const void*  ei = d_in[1];
    const float* cf = (const float*)d_in[2];
    const float* cw[4]  = {(const float*)d_in[3], (const float*)d_in[5],
                           (const float*)d_in[7], (const float*)d_in[9]};
    const float* cbi[4] = {(const float*)d_in[4], (const float*)d_in[6],
                           (const float*)d_in[8], (const float*)d_in[10]};
    const float *gw[5], *gas[5], *gad[5], *gb[5];
    for (int l = 0; l < 5; l++) {
        gw[l]  = (const float*)d_in[11 + 4 * l];
        gas[l] = (const float*)d_in[12 + 4 * l];
        gad[l] = (const float*)d_in[13 + 4 * l];
        gb[l]  = (const float*)d_in[14 + 4 * l];
    }
    float* out = (float*)d_out;

    init_detect_k<<<(NN + 255) / 256, 256>>>(ei);
    csr_count_k<<<(NE + 255) / 256, 256>>>(ei);
    csr_scan_k<<<1, 1024>>>();
    csr_fill_k<<<(ET + 255) / 256, 256>>>(ei);

    conv3x3_k<<<dim3(16, 16), 256>>>(cf, 0, 1, cw[0], cbi[0], 4);
    conv3x3_k<<<dim3(16, 32), 256>>>(nullptr, 1, 2, cw[1], cbi[1], 16);
    conv3x3_k<<<dim3(16, 64), 256>>>(nullptr, 2, 1, cw[2], cbi[2], 32);
    conv3x3_k<<<dim3(16, 24), 256>>>(nullptr, 1, 2, cw[3], cbi[3], 64);
    avgpool_k<<<24, 256>>>();
    build_in_k<<<(NN + 255) / 256, 256>>>(x);

    const int fins[5] = {34, 64, 128, 256, 128};
    const int Hs[5]   = {8, 16, 8, 8, 16};
    const int Cs[5]   = {64, 128, 256, 128, 2};

    for (int l = 0; l < 5; l++) {
        int HC = Hs[l] * Cs[l];
        dim3 gg((HC + 63) / 64, (NN + 127) / 128);
        sgemm_k<<<gg, 256>>>(gw[l], NN, fins[l], HC);
        attn_dots_k<<<NN, 256>>>(gas[l], gad[l], Hs[l], Cs[l]);
        switch (l) {
            case 0: gat_agg_k<8, 64, 2, false><<<NN, 256>>>(gb[0], x, nullptr); break;
            case 1: gat_agg_k<16, 128, 8, false><<<NN, 256>>>(gb[1], x, nullptr); break;
            case 2: gat_agg_k<8, 256, 8, false><<<NN, 256>>>(gb[2], x, nullptr); break;
            case 3: gat_agg_k<8, 128, 4, false><<<NN, 256>>>(gb[3], x, nullptr); break;
            case 4: gat_agg_k<16, 2, 2, true><<<NN, 256>>>(gb[4], x, out); break;
        }
    }
}